// round 1
// baseline (speedup 1.0000x reference)
#include <cuda_runtime.h>
#include <math.h>

#define BATCH 8
#define NPTS  4096
#define KNN   20
#define TPB   256

// Total edges
#define E_TOTAL (BATCH * NPTS * KNN)   // 655360

__global__ void sparse_graph_knn_kernel(const float* __restrict__ pc,
                                        float* __restrict__ out) {
    // dynamic smem: NPTS float4 = (x, y, z, ||p||^2)  -> 64 KB
    extern __shared__ float4 spts[];

    const int blocks_per_batch = NPTS / TPB;           // 16
    const int b    = blockIdx.x / blocks_per_batch;
    const int iblk = blockIdx.x % blocks_per_batch;

    // Stage all points of this batch into shared memory
    const float* base = pc + (size_t)b * NPTS * 3;
    for (int j = threadIdx.x; j < NPTS; j += TPB) {
        float x = base[j * 3 + 0];
        float y = base[j * 3 + 1];
        float z = base[j * 3 + 2];
        float sq = x * x + y * y + z * z;   // matches jnp.sum(p*p, -1)
        spts[j] = make_float4(x, y, z, sq);
    }
    __syncthreads();

    const int i = iblk * TPB + threadIdx.x;   // query point within batch
    const float4 q = spts[i];

    // K smallest distances, ascending; ties keep lower index (matches jax top_k)
    float kd[KNN];
    int   ki[KNN];
#pragma unroll
    for (int k = 0; k < KNN; ++k) { kd[k] = 3.0e38f; ki[k] = -1; }

#pragma unroll 4
    for (int j = 0; j < NPTS; ++j) {
        float4 p = spts[j];                    // warp-uniform -> broadcast
        float dot = q.x * p.x + q.y * p.y + q.z * p.z;
        float d2  = (q.w + p.w) - 2.0f * dot;  // same expansion as reference
        d2 = fmaxf(d2, 0.0f);
        if (d2 < kd[KNN - 1] && j != i) {
            kd[KNN - 1] = d2;
            ki[KNN - 1] = j;
            // one bubble pass restores sorted order (array was sorted before)
#pragma unroll
            for (int k = KNN - 1; k > 0; --k) {
                if (kd[k] < kd[k - 1]) {       // strict: equal dist keeps earlier index first
                    float td = kd[k]; kd[k] = kd[k - 1]; kd[k - 1] = td;
                    int   ti = ki[k]; ki[k] = ki[k - 1]; ki[k - 1] = ti;
                }
            }
        }
    }

    // Epilogue: edge indices, Gaussian attrs, s_local
    const float dk     = sqrtf(kd[KNN - 1]);        // distance to K-th NN
    const float sigma  = dk + 1e-6f;                // BETA = 1
    const float inv2s2 = 1.0f / (2.0f * sigma * sigma);

    const int   gi    = b * NPTS + i;               // batch-offset node id
    const int   ebase = gi * KNN;
    const float src_f = (float)gi;

#pragma unroll
    for (int k = 0; k < KNN; ++k) {
        float d  = sqrtf(kd[k]);                    // knn_dist (matches sqrt path)
        float at = __expf(0.0f) * 0.0f;             // placeholder avoided below
        (void)at;
        out[ebase + k]              = src_f;                          // edge_indices row 0 (src)
        out[E_TOTAL + ebase + k]    = (float)(b * NPTS + ki[k]);      // edge_indices row 1 (tgt)
        out[2 * E_TOTAL + ebase + k] = expf(-(d * d) * inv2s2);       // edge_attrs
    }
    out[3 * E_TOTAL + gi] = dk * dk;                // s_local (LAMBDA = 1)
}

extern "C" void kernel_launch(void* const* d_in, const int* in_sizes, int n_in,
                              void* d_out, int out_size) {
    (void)in_sizes; (void)n_in; (void)out_size;
    const float* pc  = (const float*)d_in[0];
    float*       out = (float*)d_out;

    const int smem = NPTS * sizeof(float4);  // 65536 B
    cudaFuncSetAttribute(sparse_graph_knn_kernel,
                         cudaFuncAttributeMaxDynamicSharedMemorySize, smem);

    dim3 grid(BATCH * (NPTS / TPB));         // 128 blocks
    sparse_graph_knn_kernel<<<grid, TPB, smem>>>(pc, out);
}

// round 5
// speedup vs baseline: 1.0982x; 1.0982x over previous
#include <cuda_runtime.h>
#include <math.h>

#define BATCH 8
#define NPTS  4096
#define KNN   20
#define TPB   256
#define QPB   (TPB / 2)          // 128 queries per block (2 threads per query)
#define TILE  8
#define HALF  (NPTS / 2)         // candidates scanned per thread
#define E_TOTAL (BATCH * NPTS * KNN)

__global__ __launch_bounds__(TPB, 2)
void knn_kernel(const float* __restrict__ pc, float* __restrict__ out) {
    extern __shared__ float4 spts[];              // 4096 x float4 = 64 KB
    // scratch aliases, used only AFTER the candidate loop (sync-guarded):
    // [TPB][KNN] float dists (20 KB) then [TPB][KNN] int indices (20 KB) = 40 KB
    float* sd = (float*)spts;
    int*   si = (int*)(sd + TPB * KNN);

    const int blocks_per_batch = NPTS / QPB;      // 32
    const int b    = blockIdx.x / blocks_per_batch;
    const int iblk = blockIdx.x % blocks_per_batch;
    const int tid  = threadIdx.x;
    const int pair = tid >> 1;                    // query slot within block
    const int par  = tid & 1;                     // candidate parity

    // Stage this batch's points (x,y,z,||p||^2) into smem
    const float* base = pc + (size_t)b * NPTS * 3;
    for (int j = tid; j < NPTS; j += TPB) {
        float x = base[j * 3 + 0];
        float y = base[j * 3 + 1];
        float z = base[j * 3 + 2];
        spts[j] = make_float4(x, y, z, x * x + y * y + z * z);
    }
    __syncthreads();

    const int i = iblk * QPB + pair;              // query point index in batch
    const float4 q = spts[i];

    float kd[KNN]; int ki[KNN];
#pragma unroll
    for (int k = 0; k < KNN; ++k) { kd[k] = 3.0e38f; ki[k] = -1; }

    // Each thread scans candidates j = 2*c + par, in tiles of 8.
    // Even lanes broadcast spts[2c], odd lanes spts[2c+1] -> different 16B banks,
    // conflict-free dual broadcast per LDS.128.
    for (int c0 = 0; c0 < HALF; c0 += TILE) {
        const int jbase = 2 * c0 + par;
        float d2[TILE];
#pragma unroll
        for (int t = 0; t < TILE; ++t) {
            float4 p = spts[jbase + 2 * t];
            float dot = fmaf(q.z, p.z, fmaf(q.y, p.y, q.x * p.x));
            d2[t] = fmaxf(fmaf(-2.0f, dot, q.w + p.w), 0.0f);
        }
        // min of the 8 (self candidate gives exactly 0 -> always routes to slow path)
        float m0 = fminf(d2[0], d2[1]);
        float m1 = fminf(d2[2], d2[3]);
        float m2 = fminf(d2[4], d2[5]);
        float m3 = fminf(d2[6], d2[7]);
        float m  = fminf(fminf(m0, m1), fminf(m2, m3));

        if (m < kd[KNN - 1]) {                    // rare slow path
#pragma unroll
            for (int t = 0; t < TILE; ++t) {
                const int j = jbase + 2 * t;
                if (d2[t] < kd[KNN - 1] && j != i) {
                    kd[KNN - 1] = d2[t];
                    ki[KNN - 1] = j;
#pragma unroll
                    for (int k = KNN - 1; k > 0; --k) {
                        if (kd[k] < kd[k - 1]) {  // strict: ties keep lower index
                            float td = kd[k]; kd[k] = kd[k - 1]; kd[k - 1] = td;
                            int   ti = ki[k]; ki[k] = ki[k - 1]; ki[k - 1] = ti;
                        }
                    }
                }
            }
        }
    }

    // Spill both half-lists to smem, then each lane merges its pair's lists.
    __syncthreads();                              // done reading spts
#pragma unroll
    for (int k = 0; k < KNN; ++k) {
        sd[tid * KNN + k] = kd[k];
        si[tid * KNN + k] = ki[k];
    }
    __syncthreads();

    const float* dA = sd + (pair * 2) * KNN;      // even-parity list (lower j's)
    const float* dB = dA + KNN;
    const int*   iA = si + (pair * 2) * KNN;
    const int*   iB = iA + KNN;

    float md[KNN]; int mi[KNN];
    int ia = 0, ib = 0;
#pragma unroll
    for (int k = 0; k < KNN; ++k) {
        float da = (ia < KNN) ? dA[ia] : 3.0e38f;
        float db = (ib < KNN) ? dB[ib] : 3.0e38f;
        int   xa = (ia < KNN) ? iA[ia] : 0x7fffffff;
        int   xb = (ib < KNN) ? iB[ib] : 0x7fffffff;
        bool takeA = (da < db) || (da == db && xa < xb);  // tie -> lower index
        md[k] = takeA ? da : db;
        mi[k] = takeA ? xa : xb;
        ia += takeA ? 1 : 0;
        ib += takeA ? 0 : 1;
    }

    // Epilogue: split the 4 output streams across the thread pair
    const float dk     = sqrtf(md[KNN - 1]);
    const float sigma  = dk + 1e-6f;
    const float inv2s2 = 1.0f / (2.0f * sigma * sigma);
    const int   gi     = b * NPTS + i;
    const int   ebase  = gi * KNN;

    if (par == 0) {
        const float srcf = (float)gi;
#pragma unroll
        for (int k = 0; k < KNN; ++k) {
            out[ebase + k]           = srcf;                       // src
            out[E_TOTAL + ebase + k] = (float)(b * NPTS + mi[k]);  // tgt
        }
    } else {
#pragma unroll
        for (int k = 0; k < KNN; ++k) {
            float d = sqrtf(md[k]);
            out[2 * E_TOTAL + ebase + k] = expf(-(d * d) * inv2s2); // attrs
        }
        out[3 * E_TOTAL + gi] = dk * dk;                            // s_local
    }
}

extern "C" void kernel_launch(void* const* d_in, const int* in_sizes, int n_in,
                              void* d_out, int out_size) {
    (void)in_sizes; (void)n_in; (void)out_size;
    const float* pc  = (const float*)d_in[0];
    float*       out = (float*)d_out;

    const int smem = NPTS * sizeof(float4);       // 64 KB
    cudaFuncSetAttribute(knn_kernel,
                         cudaFuncAttributeMaxDynamicSharedMemorySize, smem);

    dim3 grid(BATCH * (NPTS / QPB));              // 256 blocks
    knn_kernel<<<grid, TPB, smem>>>(pc, out);
}

// round 9
// speedup vs baseline: 1.1828x; 1.0770x over previous
#include <cuda_runtime.h>
#include <math.h>

#define BATCH 8
#define NPTS  4096
#define KNN   20
#define TPB   224                 // 7 warps
#define BPB   37                  // blocks per batch -> 8*37 = 296 = 2*148 (balanced)
#define TILE  8
#define HALF  (NPTS / 2)          // candidates per thread (2 threads per query)
#define E_TOTAL (BATCH * NPTS * KNN)

__global__ __launch_bounds__(TPB, 2)
void knn_kernel(const float* __restrict__ pc, float* __restrict__ out) {
    extern __shared__ float4 spts[];          // 4096 x (x,y,z, 0.5*||p||^2) = 64 KB
    // scratch aliases, used only AFTER the candidate loop (sync-guarded):
    float* sd = (float*)spts;                 // [TPB][KNN] e-values  (17.5 KB)
    int*   si = (int*)(sd + TPB * KNN);       // [TPB][KNN] indices   (17.5 KB)

    const int b    = blockIdx.x / BPB;
    const int jb   = blockIdx.x % BPB;
    const int q_lo = (jb * NPTS) / BPB;       // this block's query range in batch
    const int q_hi = ((jb + 1) * NPTS) / BPB;
    const int nq   = q_hi - q_lo;             // 110 or 111 (<= 112 pairs)
    const int tid  = threadIdx.x;
    const int pr   = tid >> 1;                // query slot within block
    const int par  = tid & 1;                 // candidate parity

    // Stage this batch's points into smem
    const float* base = pc + (size_t)b * NPTS * 3;
    for (int j = tid; j < NPTS; j += TPB) {
        float x = base[3 * j], y = base[3 * j + 1], z = base[3 * j + 2];
        spts[j] = make_float4(x, y, z, 0.5f * (x * x + y * y + z * z));
    }
    __syncthreads();

    const bool active = (pr < nq);
    const int  i = q_lo + (active ? pr : (nq - 1));   // idle pairs duplicate last query
    const float4 q = spts[i];

    // top-K by e = 0.5||p||^2 - q.p  (monotone in d2; exact float ordering)
    float kd[KNN]; int ki[KNN];
#pragma unroll
    for (int k = 0; k < KNN; ++k) { kd[k] = 3.0e38f; ki[k] = -1; }

    for (int c0 = 0; c0 < HALF; c0 += TILE) {
        // shared pair threshold (partner lane serves the SAME query).
        // Stale-by-one-tile is conservative (kd[19] decreases monotonically).
        float thr = fminf(kd[KNN - 1], __shfl_xor_sync(0xffffffffu, kd[KNN - 1], 1));

        const int jbase = 2 * c0 + par;
        float e[TILE];
#pragma unroll
        for (int t = 0; t < TILE; ++t) {
            float4 p = spts[jbase + 2 * t];
            e[t] = fmaf(-q.x, p.x, fmaf(-q.y, p.y, fmaf(-q.z, p.z, p.w)));
        }
        float m0 = fminf(e[0], e[1]);
        float m1 = fminf(e[2], e[3]);
        float m2 = fminf(e[4], e[5]);
        float m3 = fminf(e[6], e[7]);
        float m  = fminf(fminf(m0, m1), fminf(m2, m3));

        if (m < thr) {                         // tile-level trigger (tight threshold)
#pragma unroll
            for (int t = 0; t < TILE; ++t) {
                const int j = jbase + 2 * t;
                // per-candidate test vs CURRENT kd[19]: safe (>=20 own cands smaller)
                if (e[t] < kd[KNN - 1] && j != i) {
                    kd[KNN - 1] = e[t];
                    ki[KNN - 1] = j;
#pragma unroll
                    for (int k = KNN - 1; k > 0; --k) {
                        if (kd[k] < kd[k - 1]) {   // strict: ties keep lower index
                            float td = kd[k]; kd[k] = kd[k - 1]; kd[k - 1] = td;
                            int   ti = ki[k]; ki[k] = ki[k - 1]; ki[k - 1] = ti;
                        }
                    }
                }
            }
        }
    }

    // Spill both half-lists, then each lane merges its pair's lists.
    __syncthreads();                           // done reading spts
#pragma unroll
    for (int k = 0; k < KNN; ++k) {
        sd[tid * KNN + k] = kd[k];
        si[tid * KNN + k] = ki[k];
    }
    __syncthreads();

    const float* dA = sd + (pr * 2) * KNN;     // even-parity list
    const float* dB = dA + KNN;
    const int*   iA = si + (pr * 2) * KNN;
    const int*   iB = iA + KNN;

    float md[KNN]; int mi[KNN];
    int ia = 0, ib = 0;
#pragma unroll
    for (int k = 0; k < KNN; ++k) {
        float da = (ia < KNN) ? dA[ia] : 3.0e38f;
        float db = (ib < KNN) ? dB[ib] : 3.0e38f;
        int   xa = (ia < KNN) ? iA[ia] : 0x7fffffff;
        int   xb = (ib < KNN) ? iB[ib] : 0x7fffffff;
        bool takeA = (da < db) || (da == db && xa < xb);
        md[k] = takeA ? da : db;
        mi[k] = takeA ? xa : xb;
        ia += takeA ? 1 : 0;
        ib += takeA ? 0 : 1;
    }

    if (!active) return;

    // Reconstruct exact d2 = 2*(0.5||q||^2 + e), clamped at 0
    const float d2K    = fmaxf(2.0f * (q.w + md[KNN - 1]), 0.0f);
    const float dk     = sqrtf(d2K);
    const float sigma  = dk + 1e-6f;
    const float inv2s2 = 1.0f / (2.0f * sigma * sigma);
    const int   gi     = b * NPTS + i;
    const int   ebase  = gi * KNN;

    if (par == 0) {
        const float srcf = (float)gi;
#pragma unroll
        for (int k = 0; k < KNN; ++k) {
            out[ebase + k]           = srcf;                       // src
            out[E_TOTAL + ebase + k] = (float)(b * NPTS + mi[k]);  // tgt
        }
    } else {
#pragma unroll
        for (int k = 0; k < KNN; ++k) {
            float d2 = fmaxf(2.0f * (q.w + md[k]), 0.0f);
            float d  = sqrtf(d2);
            out[2 * E_TOTAL + ebase + k] = expf(-(d * d) * inv2s2); // attrs
        }
        out[3 * E_TOTAL + gi] = dk * dk;                            // s_local
    }
}

extern "C" void kernel_launch(void* const* d_in, const int* in_sizes, int n_in,
                              void* d_out, int out_size) {
    (void)in_sizes; (void)n_in; (void)out_size;
    const float* pc  = (const float*)d_in[0];
    float*       out = (float*)d_out;

    const int smem = NPTS * sizeof(float4);    // 64 KB
    cudaFuncSetAttribute(knn_kernel,
                         cudaFuncAttributeMaxDynamicSharedMemorySize, smem);

    dim3 grid(BATCH * BPB);                    // 296 blocks = 2 per SM, balanced
    knn_kernel<<<grid, TPB, smem>>>(pc, out);
}

// round 10
// speedup vs baseline: 1.1985x; 1.0133x over previous
#include <cuda_runtime.h>
#include <math.h>

#define BATCH 8
#define NPTS  4096
#define KNN   20
#define TPB   224                 // 7 warps
#define BPB   37                  // 8*37 = 296 = 2*148 blocks (balanced waves)
#define TILE  8
#define HALF  (NPTS / 2)          // candidates per thread (2 threads per query)
#define E_TOTAL (BATCH * NPTS * KNN)

__global__ __launch_bounds__(TPB, 2)
void knn_kernel(const float* __restrict__ pc, float* __restrict__ out) {
    extern __shared__ float4 spts[];          // 4096 x (x,y,z, 0.5*||p||^2) = 64 KB
    // scratch aliases, used only AFTER the candidate loop (sync-guarded):
    float* sd = (float*)spts;                 // [TPB][KNN] e-values
    int*   si = (int*)(sd + TPB * KNN);       // [TPB][KNN] indices

    const int b    = blockIdx.x / BPB;
    const int jb   = blockIdx.x % BPB;
    const int q_lo = (jb * NPTS) / BPB;
    const int q_hi = ((jb + 1) * NPTS) / BPB;
    const int nq   = q_hi - q_lo;             // 110 or 111
    const int tid  = threadIdx.x;
    const int pr   = tid >> 1;                // query slot within block
    const int par  = tid & 1;                 // candidate parity

    const float* base = pc + (size_t)b * NPTS * 3;
    for (int j = tid; j < NPTS; j += TPB) {
        float x = base[3 * j], y = base[3 * j + 1], z = base[3 * j + 2];
        spts[j] = make_float4(x, y, z, 0.5f * (x * x + y * y + z * z));
    }
    __syncthreads();

    const bool active = (pr < nq);
    const int  i = q_lo + (active ? pr : (nq - 1));
    const float4 q = spts[i];

    // top-K by e = 0.5||p||^2 - q.p  (monotone in d2; exact float ordering)
    float kd[KNN]; int ki[KNN];
#pragma unroll
    for (int k = 0; k < KNN; ++k) { kd[k] = 3.0e38f; ki[k] = -1; }

    for (int c0 = 0; c0 < HALF; c0 += TILE) {
        // Merged-pair threshold: min of both lanes' kd[19] (partner stale by one
        // tile -> conservative upper bound on the query's merged 20th).
        // A candidate with e >= thr can NEVER be in the final merged top-20,
        // so it is both the tile trigger AND the per-candidate insert gate.
        float thr = fminf(kd[KNN - 1], __shfl_xor_sync(0xffffffffu, kd[KNN - 1], 1));

        const int jbase = 2 * c0 + par;
        float e[TILE];
#pragma unroll
        for (int t = 0; t < TILE; ++t) {
            float4 p = spts[jbase + 2 * t];
            e[t] = fmaf(-q.x, p.x, fmaf(-q.y, p.y, fmaf(-q.z, p.z, p.w)));
        }
        float m0 = fminf(e[0], e[1]);
        float m1 = fminf(e[2], e[3]);
        float m2 = fminf(e[4], e[5]);
        float m3 = fminf(e[6], e[7]);
        float m  = fminf(fminf(m0, m1), fminf(m2, m3));

        if (m < thr) {                         // slow path
#pragma unroll
            for (int t = 0; t < TILE; ++t) {
                const int j = jbase + 2 * t;
                if (e[t] < thr && j != i) {    // merged-threshold insert gate
                    kd[KNN - 1] = e[t];
                    ki[KNN - 1] = j;
#pragma unroll
                    for (int k = KNN - 1; k > 0; --k) {
                        if (kd[k] < kd[k - 1]) {   // strict: ties keep lower index
                            float td = kd[k]; kd[k] = kd[k - 1]; kd[k - 1] = td;
                            int   ti = ki[k]; ki[k] = ki[k - 1]; ki[k - 1] = ti;
                        }
                    }
                }
            }
        }
    }

    // Spill both half-lists, then each lane merges its pair's lists.
    __syncthreads();                           // done reading spts
#pragma unroll
    for (int k = 0; k < KNN; ++k) {
        sd[tid * KNN + k] = kd[k];
        si[tid * KNN + k] = ki[k];
    }
    __syncthreads();

    const float* dA = sd + (pr * 2) * KNN;
    const float* dB = dA + KNN;
    const int*   iA = si + (pr * 2) * KNN;
    const int*   iB = iA + KNN;

    float md[KNN]; int mi[KNN];
    int ia = 0, ib = 0;
#pragma unroll
    for (int k = 0; k < KNN; ++k) {
        float da = (ia < KNN) ? dA[ia] : 3.0e38f;
        float db = (ib < KNN) ? dB[ib] : 3.0e38f;
        int   xa = (ia < KNN) ? iA[ia] : 0x7fffffff;
        int   xb = (ib < KNN) ? iB[ib] : 0x7fffffff;
        bool takeA = (da < db) || (da == db && xa < xb);
        md[k] = takeA ? da : db;
        mi[k] = takeA ? xa : xb;
        ia += takeA ? 1 : 0;
        ib += takeA ? 0 : 1;
    }

    if (!active) return;

    // Reconstruct exact d2 = 2*(0.5||q||^2 + e), clamped at 0
    const float d2K    = fmaxf(2.0f * (q.w + md[KNN - 1]), 0.0f);
    const float dk     = sqrtf(d2K);
    const float sigma  = dk + 1e-6f;
    const float inv2s2 = 1.0f / (2.0f * sigma * sigma);
    const int   gi     = b * NPTS + i;
    const int   ebase  = gi * KNN;

    if (par == 0) {
        const float srcf = (float)gi;
#pragma unroll
        for (int k = 0; k < KNN; ++k) {
            out[ebase + k]           = srcf;                       // src
            out[E_TOTAL + ebase + k] = (float)(b * NPTS + mi[k]);  // tgt
        }
    } else {
#pragma unroll
        for (int k = 0; k < KNN; ++k) {
            float d2 = fmaxf(2.0f * (q.w + md[k]), 0.0f);
            float d  = sqrtf(d2);
            out[2 * E_TOTAL + ebase + k] = expf(-(d * d) * inv2s2); // attrs
        }
        out[3 * E_TOTAL + gi] = dk * dk;                            // s_local
    }
}

extern "C" void kernel_launch(void* const* d_in, const int* in_sizes, int n_in,
                              void* d_out, int out_size) {
    (void)in_sizes; (void)n_in; (void)out_size;
    const float* pc  = (const float*)d_in[0];
    float*       out = (float*)d_out;

    const int smem = NPTS * sizeof(float4);    // 64 KB
    cudaFuncSetAttribute(knn_kernel,
                         cudaFuncAttributeMaxDynamicSharedMemorySize, smem);

    dim3 grid(BATCH * BPB);                    // 296 blocks
    knn_kernel<<<grid, TPB, smem>>>(pc, out);
}

// round 12
// speedup vs baseline: 3.4616x; 2.8882x over previous
#include <cuda_runtime.h>
#include <math.h>

#define BATCH 8
#define NPTS  4096
#define KNN   20
#define TPB   512                  // 16 warps = 16 queries per block
#define WPB   (TPB / 32)
#define BPB   (NPTS / WPB)         // 256 blocks per batch
#define E_TOTAL (BATCH * NPTS * KNN)
#define FULL 0xffffffffu

__global__ __launch_bounds__(TPB, 2)
void knn_kernel(const float* __restrict__ pc, float* __restrict__ out) {
    extern __shared__ float4 spts[];           // 4096 x (x,y,z, 0.5*||p||^2) = 64 KB

    const int b   = blockIdx.x / BPB;
    const int jb  = blockIdx.x % BPB;
    const int tid = threadIdx.x;
    const int wid  = tid >> 5;
    const int lane = tid & 31;

    // Stage this batch's points into smem (coalesced: 384B contiguous per warp-iter)
    const float* base = pc + (size_t)b * NPTS * 3;
    for (int j = tid; j < NPTS; j += TPB) {
        float x = base[3 * j], y = base[3 * j + 1], z = base[3 * j + 2];
        spts[j] = make_float4(x, y, z, 0.5f * (x * x + y * y + z * z));
    }
    __syncthreads();

    const int i = jb * WPB + wid;              // this warp's query (one per warp)
    const float4 q = spts[i];                  // lane-uniform -> LDS broadcast

    // Warp-distributed sorted list: lane l holds l-th smallest e seen so far.
    // e = 0.5||p||^2 - q.p (monotone in d2, exact-float ordering).
    // Threshold = lane 19's value (20th smallest).
    float held = 3.0e38f;
    int   hidx = 0x7fffffff;
    float thr  = 3.0e38f;

    for (int c0 = 0; c0 < NPTS; c0 += 128) {
        float e0, e1, e2, e3;
        bool  p0, p1, p2, p3;
        {
            float4 a = spts[c0 + lane];
            float4 bb = spts[c0 + 32 + lane];
            float4 c = spts[c0 + 64 + lane];
            float4 d = spts[c0 + 96 + lane];
            e0 = fmaf(-q.x, a.x,  fmaf(-q.y, a.y,  fmaf(-q.z, a.z,  a.w)));
            e1 = fmaf(-q.x, bb.x, fmaf(-q.y, bb.y, fmaf(-q.z, bb.z, bb.w)));
            e2 = fmaf(-q.x, c.x,  fmaf(-q.y, c.y,  fmaf(-q.z, c.z,  c.w)));
            e3 = fmaf(-q.x, d.x,  fmaf(-q.y, d.y,  fmaf(-q.z, d.z,  d.w)));
            p0 = (e0 < thr) && (c0 + lane      != i);
            p1 = (e1 < thr) && (c0 + 32 + lane != i);
            p2 = (e2 < thr) && (c0 + 64 + lane != i);
            p3 = (e3 < thr) && (c0 + 96 + lane != i);
        }
        if (__any_sync(FULL, p0 | p1 | p2 | p3)) {
#pragma unroll
            for (int u = 0; u < 4; ++u) {
                bool  pu = (u == 0) ? p0 : (u == 1) ? p1 : (u == 2) ? p2 : p3;
                float eu = (u == 0) ? e0 : (u == 1) ? e1 : (u == 2) ? e2 : e3;
                unsigned m = __ballot_sync(FULL, pu);
                const int jb0 = c0 + u * 32;
                while (m) {
                    const int src = __ffs(m) - 1;
                    m &= m - 1;
                    const float v = __shfl_sync(FULL, eu, src);   // uniform
                    if (v < thr) {                                 // recheck (thr tightens)
                        const int vj = jb0 + src;
                        // warp-parallel sorted insert (shift-by-one above pos)
                        bool keep = (held <= v);   // ties: earlier (lower j) stays first
                        unsigned bm = __ballot_sync(FULL, keep);
                        float up_v = __shfl_up_sync(FULL, held, 1);
                        int   up_i = __shfl_up_sync(FULL, hidx, 1);
                        bool prevkeep = (lane == 0) ? true : ((bm >> (lane - 1)) & 1u);
                        if (!keep) {
                            held = prevkeep ? v  : up_v;
                            hidx = prevkeep ? vj : up_i;
                        }
                        thr = __shfl_sync(FULL, held, KNN - 1);
                    }
                }
            }
        }
    }

    // Epilogue: lanes 0..19 hold the sorted top-20 (e ascending, ties by j).
    const float eK     = __shfl_sync(FULL, held, KNN - 1);
    const float d2K    = fmaxf(2.0f * (q.w + eK), 0.0f);
    const float dk     = sqrtf(d2K);
    const float sigma  = dk + 1e-6f;
    const float inv2s2 = 1.0f / (2.0f * sigma * sigma);

    const int gi    = b * NPTS + i;
    const int ebase = gi * KNN;

    if (lane < KNN) {
        float d2 = fmaxf(2.0f * (q.w + held), 0.0f);
        out[ebase + lane]               = (float)gi;                    // src
        out[E_TOTAL + ebase + lane]     = (float)(b * NPTS + hidx);     // tgt
        out[2 * E_TOTAL + ebase + lane] = expf(-d2 * inv2s2);           // attrs
    }
    if (lane == 0)
        out[3 * E_TOTAL + gi] = dk * dk;                                // s_local
}

extern "C" void kernel_launch(void* const* d_in, const int* in_sizes, int n_in,
                              void* d_out, int out_size) {
    (void)in_sizes; (void)n_in; (void)out_size;
    const float* pc  = (const float*)d_in[0];
    float*       out = (float*)d_out;

    const int smem = NPTS * sizeof(float4);    // 64 KB
    cudaFuncSetAttribute(knn_kernel,
                         cudaFuncAttributeMaxDynamicSharedMemorySize, smem);

    dim3 grid(BATCH * BPB);                    // 2048 blocks, 16 queries each
    knn_kernel<<<grid, TPB, smem>>>(pc, out);
}